// round 3
// baseline (speedup 1.0000x reference)
#include <cuda_runtime.h>
#include <math.h>

#define VOLD   256
#define NGAUSS 4000
#define TS     8
#define TPA    32                    // tiles per axis
#define NTILES 32768
#define CAP    32                    // max gaussians per tile (Poisson mean ~5)
#define SLICE  24                    // floats per slice: wx[8] wy[8] wz[8]

// ---------------------------------------------------------------------------
// Static device scratch. Zero-initialized at module load; gather restores
// g_cnt to zero at the end of every launch, so the invariant holds across
// the correctness run, graph capture, and all replays.
// ---------------------------------------------------------------------------
__device__ int g_cnt[NTILES];
__device__ __align__(16) float g_slice[(size_t)NTILES * CAP * SLICE]; // 96 MB

// ---------------------------------------------------------------------------
// Kernel 1: per-Gaussian separable weights + direct slice scatter into tiles.
// One block per Gaussian. Tile bodies are distributed round-robin over the
// 4 warps via a counter nest (no integer division anywhere).
// ---------------------------------------------------------------------------
__global__ __launch_bounds__(128) void prep_kernel(
    const float* __restrict__ centers,
    const float* __restrict__ sigmas,
    const float* __restrict__ intens)
{
    const int g    = blockIdx.x;
    const int t    = threadIdx.x;
    const int warp = t >> 5;
    const int lane = t & 31;

    __shared__ float sw[3][32];
    __shared__ int s_tmin[3], s_tmax[3], s_start[3];

    const float sig    = sigmas[g];
    const float inv2s2 = 0.5f / (sig * sig);
    const float I      = intens[g];
    const float cut    = 3.0f * sig * 255.0f;

    if (t < 96) {
        const int axis = t >> 5;
        const int o    = t & 31;

        const float cn = centers[3 * g + axis];
        const float cv = cn * 255.0f;

        const float minf = fmaxf(cv - cut, 0.0f);
        const float maxf = fminf(cv + cut, 255.0f);
        const int   mini = (int)floorf(minf);
        const int   maxi = min((int)floorf(maxf) + 1, VOLD);   // exclusive
        const int   start = min(mini, VOLD - 32);

        const int idx = start + o;
        float w = 0.0f;
        if (idx >= mini && idx < maxi) {
            const float d = (float)idx * (1.0f / 255.0f) - cn;
            w = expf(-d * d * inv2s2);
        }
        if (axis == 0) w *= I;
        sw[axis][o] = w;

        if (o == 0) {
            s_tmin[axis]  = mini >> 3;
            s_tmax[axis]  = (maxi - 1) >> 3;
            s_start[axis] = start;
        }
    }
    __syncthreads();

    const int x0 = s_tmin[0], x1 = s_tmax[0];
    const int y0 = s_tmin[1], y1 = s_tmax[1];
    const int z0 = s_tmin[2], z1 = s_tmax[2];
    const int st0 = s_start[0], st1 = s_start[1], st2 = s_start[2];

    // Per-lane slice role (lanes 0..5 write one float4 each = 24 floats)
    const int axis = lane >> 1;          // 0,0,1,1,2,2
    const int o4   = (lane & 1) * 4;     // 0 or 4
    const int st   = (axis == 0) ? st0 : ((axis == 1) ? st1 : st2);

    int c = 0;
    for (int tx = x0; tx <= x1; ++tx)
    for (int ty = y0; ty <= y1; ++ty)
    for (int tz = z0; tz <= z1; ++tz) {
        if ((c++ & 3) == warp) {
            const int tile = ((tx << 5) + ty) * TPA + tz;
            int slot;
            if (lane == 0) slot = atomicAdd(&g_cnt[tile], 1);
            slot = __shfl_sync(0xffffffffu, slot, 0);
            if (slot < CAP && lane < 6) {
                const int tb = (axis == 0) ? tx : ((axis == 1) ? ty : tz);
                const int k  = (tb << 3) + o4 - st;     // slice offset - start
                float4 v;
                v.x = ((unsigned)(k + 0) < 32u) ? sw[axis][k + 0] : 0.f;
                v.y = ((unsigned)(k + 1) < 32u) ? sw[axis][k + 1] : 0.f;
                v.z = ((unsigned)(k + 2) < 32u) ? sw[axis][k + 2] : 0.f;
                v.w = ((unsigned)(k + 3) < 32u) ? sw[axis][k + 3] : 0.f;
                float* dst = g_slice + ((size_t)tile * CAP + slot) * SLICE + lane * 4;
                *(float4*)dst = v;
            }
        }
    }
}

// ---------------------------------------------------------------------------
// Kernel 2: gather. One block per 8x8x8 tile; barrier-free inner loop reading
// pre-materialized slices; each thread accumulates one z-quad in registers
// and writes a single float4. Self-cleans the tile counter.
// ---------------------------------------------------------------------------
__global__ __launch_bounds__(128) void gather_kernel(float* __restrict__ vol) {
    const int tile = blockIdx.x;
    const int t    = threadIdx.x;

    const int tzi = tile & (TPA - 1);
    const int tyi = (tile >> 5) & (TPA - 1);
    const int txi = tile >> 10;

    const int cnt = min(g_cnt[tile], CAP);
    __syncthreads();                     // all threads have read cnt
    if (t == 0) g_cnt[tile] = 0;         // restore invariant for next launch

    // thread -> voxel quad: x = t>>4, y = (t>>1)&7, z in [zb, zb+4)
    const int x  = t >> 4;
    const int y  = (t >> 1) & 7;
    const int zb = (t & 1) * 4;

    const float* __restrict__ base = g_slice + (size_t)tile * CAP * SLICE;

    float a0 = 0.f, a1 = 0.f, a2 = 0.f, a3 = 0.f;

#pragma unroll 2
    for (int p = 0; p < cnt; ++p) {
        const float* s = base + p * SLICE;
        const float  f = s[x] * s[8 + y];
        const float4 wz = *(const float4*)(s + 16 + zb);
        a0 = fmaf(f, wz.x, a0);
        a1 = fmaf(f, wz.y, a1);
        a2 = fmaf(f, wz.z, a2);
        a3 = fmaf(f, wz.w, a3);
    }

    const size_t off = (((size_t)(txi * TS + x) * VOLD) + (tyi * TS + y)) * VOLD
                       + tzi * TS + zb;
    *(float4*)(vol + off) = make_float4(a0, a1, a2, a3);
}

// ---------------------------------------------------------------------------
extern "C" void kernel_launch(void* const* d_in, const int* in_sizes, int n_in,
                              void* d_out, int out_size) {
    const float* centers = (const float*)d_in[0];
    const float* sigmas  = (const float*)d_in[1];
    const float* intens  = (const float*)d_in[2];
    float* vol = (float*)d_out;

    prep_kernel<<<NGAUSS, 128>>>(centers, sigmas, intens);
    gather_kernel<<<NTILES, 128>>>(vol);
}

// round 4
// speedup vs baseline: 4.2940x; 4.2940x over previous
#include <cuda_runtime.h>
#include <math.h>

#define VOLD   256
#define NGAUSS 4000
#define TS     8
#define TPA    32                    // tiles per axis
#define NTILES 32768
#define CAP    32                    // max gaussians per tile (empirical max well below)
#define SLICE  24                    // floats per pair slice: wx[8] wy[8] wz[8]

// ---------------------------------------------------------------------------
// Static device scratch. Zero-initialized at module load; gather restores
// g_cnt to zero every launch, so the invariant holds across correctness run,
// graph capture, and all replays.
// ---------------------------------------------------------------------------
__device__ int g_cnt[NTILES];
__device__ __align__(16) float g_slice[(size_t)NTILES * CAP * SLICE];  // 96 MB

// ---------------------------------------------------------------------------
// Kernel 1: per-Gaussian separable weights, then thread-per-tile binning:
// one atomicAdd + one 24-float slice write per (gaussian, tile) pair.
// ---------------------------------------------------------------------------
__global__ __launch_bounds__(128) void prep_kernel(
    const float* __restrict__ centers,
    const float* __restrict__ sigmas,
    const float* __restrict__ intens)
{
    const int g = blockIdx.x;
    const int t = threadIdx.x;

    __shared__ float sw[3][32];
    __shared__ int s_tmin[3], s_tn[3], s_start[3];

    const float sig    = sigmas[g];
    const float inv2s2 = 0.5f / (sig * sig);
    const float I      = intens[g];
    const float cut    = 3.0f * sig * 255.0f;

    if (t < 96) {
        const int axis = t >> 5;
        const int o    = t & 31;

        const float cn = centers[3 * g + axis];
        const float cv = cn * 255.0f;

        const float minf = fmaxf(cv - cut, 0.0f);
        const float maxf = fminf(cv + cut, 255.0f);
        const int   mini = (int)floorf(minf);
        const int   maxi = min((int)floorf(maxf) + 1, VOLD);   // exclusive
        const int   start = min(mini, VOLD - 32);

        const int idx = start + o;
        float w = 0.0f;
        if (idx >= mini && idx < maxi) {
            const float d = (float)idx * (1.0f / 255.0f) - cn;
            w = expf(-d * d * inv2s2);
        }
        if (axis == 0) w *= I;
        sw[axis][o] = w;

        if (o == 0) {
            const int tmin = mini >> 3;
            const int tmax = (maxi - 1) >> 3;
            s_tmin[axis]  = tmin;
            s_tn[axis]    = tmax - tmin + 1;
            s_start[axis] = start;
        }
    }
    __syncthreads();

    const int x0 = s_tmin[0], y0 = s_tmin[1], z0 = s_tmin[2];
    const int nx = s_tn[0],   ny = s_tn[1],   nz = s_tn[2];
    const int st0 = s_start[0], st1 = s_start[1], st2 = s_start[2];

    const int total = nx * ny * nz;
    for (int i = t; i < total; i += 128) {
        const int iz = i % nz;
        const int r  = i / nz;
        const int iy = r % ny;
        const int ix = r / ny;
        const int tx = x0 + ix, ty = y0 + iy, tz = z0 + iz;
        const int tile = ((tx << 5) + ty) * TPA + tz;

        const int slot = atomicAdd(&g_cnt[tile], 1);
        if (slot < CAP) {
            float* dst = g_slice + ((size_t)tile * CAP + slot) * SLICE;
            const int k0 = (tx << 3) - st0;     // offset of tile x-origin in window
            const int k1 = (ty << 3) - st1;
            const int k2 = (tz << 3) - st2;
#pragma unroll
            for (int axis = 0; axis < 3; ++axis) {
                const int kb = (axis == 0) ? k0 : ((axis == 1) ? k1 : k2);
#pragma unroll
                for (int h = 0; h < 2; ++h) {
                    const int k = kb + 4 * h;
                    float4 v;
                    v.x = ((unsigned)(k + 0) < 32u) ? sw[axis][k + 0] : 0.f;
                    v.y = ((unsigned)(k + 1) < 32u) ? sw[axis][k + 1] : 0.f;
                    v.z = ((unsigned)(k + 2) < 32u) ? sw[axis][k + 2] : 0.f;
                    v.w = ((unsigned)(k + 3) < 32u) ? sw[axis][k + 3] : 0.f;
                    *(float4*)(dst + axis * 8 + 4 * h) = v;
                }
            }
        }
    }
}

// ---------------------------------------------------------------------------
// Kernel 2: gather. One block per 8x8x8 tile. Coalesced bulk stage of all
// slices into shared (one barrier), then register accumulation from shared,
// single float4 store per thread. Self-cleans the tile counter.
// ---------------------------------------------------------------------------
__global__ __launch_bounds__(128) void gather_kernel(float* __restrict__ vol) {
    const int tile = blockIdx.x;
    const int t    = threadIdx.x;

    __shared__ __align__(16) float sh[CAP * SLICE];

    const int cnt = min(g_cnt[tile], CAP);

    // Coalesced stage: cnt*6 contiguous float4s
    const float4* __restrict__ src =
        (const float4*)(g_slice + (size_t)tile * CAP * SLICE);
    const int n4 = cnt * (SLICE / 4);
    for (int i = t; i < n4; i += 128) ((float4*)sh)[i] = src[i];

    __syncthreads();                      // staging done; all threads read cnt
    if (t == 0) g_cnt[tile] = 0;          // restore invariant for next launch

    // thread -> voxel quad: x = t>>4, y = (t>>1)&7, z in [zb, zb+4)
    const int x  = t >> 4;
    const int y  = (t >> 1) & 7;
    const int zb = (t & 1) * 4;

    float a0 = 0.f, a1 = 0.f, a2 = 0.f, a3 = 0.f;

#pragma unroll 4
    for (int p = 0; p < cnt; ++p) {
        const float* s = sh + p * SLICE;
        const float  f = s[x] * s[8 + y];
        const float4 wz = *(const float4*)(s + 16 + zb);
        a0 = fmaf(f, wz.x, a0);
        a1 = fmaf(f, wz.y, a1);
        a2 = fmaf(f, wz.z, a2);
        a3 = fmaf(f, wz.w, a3);
    }

    const int tzi = tile & (TPA - 1);
    const int tyi = (tile >> 5) & (TPA - 1);
    const int txi = tile >> 10;
    const size_t off = (((size_t)(txi * TS + x) * VOLD) + (tyi * TS + y)) * VOLD
                       + tzi * TS + zb;
    *(float4*)(vol + off) = make_float4(a0, a1, a2, a3);
}

// ---------------------------------------------------------------------------
extern "C" void kernel_launch(void* const* d_in, const int* in_sizes, int n_in,
                              void* d_out, int out_size) {
    const float* centers = (const float*)d_in[0];
    const float* sigmas  = (const float*)d_in[1];
    const float* intens  = (const float*)d_in[2];
    float* vol = (float*)d_out;

    prep_kernel<<<NGAUSS, 128>>>(centers, sigmas, intens);
    gather_kernel<<<NTILES, 128>>>(vol);
}